// round 1
// baseline (speedup 1.0000x reference)
#include <cuda_runtime.h>

#define B_   2
#define LQ   2048
#define LKV  2048
#define D    1024
#define NH   16
#define HD   64
#define MTOT (B_ * LQ)
#define EPS  1e-5f

// Scratch (allocation-free): head-major Q/K/V, ctx, pre-LN x
__device__ float g_Q[B_ * NH * LQ * HD];
__device__ float g_K[B_ * NH * LKV * HD];
__device__ float g_V[B_ * NH * LKV * HD];
__device__ float g_ctx[MTOT * D];
__device__ float g_X[MTOT * D];

// ---------------------------------------------------------------------------
// Tiled SGEMM: C = A[M,1024] @ W[1024,1024] + bias
// MODE 0: A = param, output scattered head-major into g_Q/g_K/g_V (dest_sel)
// MODE 1: A = g_ctx, output = g_X = resid + A@W + bias
// Tile 64x64, BK=16, 256 threads, 4x4 micro-tile per thread.
// ---------------------------------------------------------------------------
template <int MODE>
__global__ __launch_bounds__(256) void gemm_kernel(
    const float* __restrict__ Ain, const float* __restrict__ W,
    const float* __restrict__ bias, const float* __restrict__ resid,
    int dest_sel)
{
    const float* A = (MODE == 1) ? g_ctx : Ain;

    __shared__ float As[16][65];   // transposed [k][m], padded
    __shared__ float Bs[16][64];   // [k][n]

    const int t  = threadIdx.x;
    const int tx = t & 15;         // n direction
    const int ty = t >> 4;         // m direction
    const int n0 = blockIdx.x * 64;
    const int m0 = blockIdx.y * 64;

    const int ar = t >> 2;          // 0..63 (m row in tile)
    const int ac = (t & 3) << 2;    // 0..12 (k col, float4)
    const int bk = t >> 4;          // 0..15 (k row)
    const int bc = (t & 15) << 2;   // 0..60 (n col, float4)

    const float* aptr = A + (m0 + ar) * D + ac;
    const float* bptr = W + bk * D + n0 + bc;

    float acc[4][4] = {};

    for (int kb = 0; kb < D; kb += 16) {
        float4 av = *(const float4*)(aptr + kb);
        float4 bv = *(const float4*)(bptr + (size_t)kb * D);
        As[ac + 0][ar] = av.x;
        As[ac + 1][ar] = av.y;
        As[ac + 2][ar] = av.z;
        As[ac + 3][ar] = av.w;
        *(float4*)&Bs[bk][bc] = bv;
        __syncthreads();

#pragma unroll
        for (int k = 0; k < 16; k++) {
            float4 b4 = *(const float4*)&Bs[k][tx << 2];
            float a0 = As[k][(ty << 2) + 0];
            float a1 = As[k][(ty << 2) + 1];
            float a2 = As[k][(ty << 2) + 2];
            float a3 = As[k][(ty << 2) + 3];
            acc[0][0] += a0 * b4.x; acc[0][1] += a0 * b4.y; acc[0][2] += a0 * b4.z; acc[0][3] += a0 * b4.w;
            acc[1][0] += a1 * b4.x; acc[1][1] += a1 * b4.y; acc[1][2] += a1 * b4.z; acc[1][3] += a1 * b4.w;
            acc[2][0] += a2 * b4.x; acc[2][1] += a2 * b4.y; acc[2][2] += a2 * b4.z; acc[2][3] += a2 * b4.w;
            acc[3][0] += a3 * b4.x; acc[3][1] += a3 * b4.y; acc[3][2] += a3 * b4.z; acc[3][3] += a3 * b4.w;
        }
        __syncthreads();
    }

    float4 bias4 = *(const float4*)&bias[n0 + (tx << 2)];

    if (MODE == 0) {
        float* C = (dest_sel == 0) ? g_Q : (dest_sel == 1) ? g_K : g_V;
        const int b     = m0 / LQ;        // 64 | 2048 -> whole block same batch
        const int lbase = m0 % LQ;
        const int h     = n0 >> 6;        // whole block same head (64-wide N tile)
#pragma unroll
        for (int i = 0; i < 4; i++) {
            int l = lbase + (ty << 2) + i;
            float4 o;
            o.x = acc[i][0] + bias4.x;
            o.y = acc[i][1] + bias4.y;
            o.z = acc[i][2] + bias4.z;
            o.w = acc[i][3] + bias4.w;
            *(float4*)&C[(((size_t)(b * NH + h)) * LQ + l) * HD + (tx << 2)] = o;
        }
    } else {
#pragma unroll
        for (int i = 0; i < 4; i++) {
            int m = m0 + (ty << 2) + i;
            float4 r4 = *(const float4*)&resid[(size_t)m * D + n0 + (tx << 2)];
            float4 o;
            o.x = acc[i][0] + bias4.x + r4.x;
            o.y = acc[i][1] + bias4.y + r4.y;
            o.z = acc[i][2] + bias4.z + r4.z;
            o.w = acc[i][3] + bias4.w + r4.w;
            *(float4*)&g_X[(size_t)m * D + n0 + (tx << 2)] = o;
        }
    }
}

// ---------------------------------------------------------------------------
// Flash attention: per block = one (b,h) x 64 q-rows. BN=32 kv per step.
// 256 threads as 16(tx: kv/hd cols) x 16(ty: q rows), online softmax.
// ---------------------------------------------------------------------------
__global__ __launch_bounds__(256) void attn_kernel()
{
    __shared__ float Qs[64][65];
    __shared__ float Ks[32][65];
    __shared__ float Vs[32][64];
    __shared__ float Ps[64][33];

    const int bh = blockIdx.y;
    const int q0 = blockIdx.x * 64;
    const float* Qp = g_Q + ((size_t)bh * LQ + q0) * HD;
    const float* Kp = g_K + (size_t)bh * LKV * HD;
    const float* Vp = g_V + (size_t)bh * LKV * HD;

    const int t  = threadIdx.x;
    const int tx = t & 15;
    const int ty = t >> 4;

    // Load Q tile 64x64 (1024 float4, 4 per thread)
#pragma unroll
    for (int i = 0; i < 4; i++) {
        int idx = t + i * 256;
        int r = idx >> 4, c = (idx & 15) << 2;
        float4 v = *(const float4*)&Qp[r * HD + c];
        Qs[r][c + 0] = v.x; Qs[r][c + 1] = v.y; Qs[r][c + 2] = v.z; Qs[r][c + 3] = v.w;
    }

    float m_i[4], l_i[4], O[4][4] = {};
#pragma unroll
    for (int i = 0; i < 4; i++) { m_i[i] = -1e30f; l_i[i] = 0.f; }

    for (int kv0 = 0; kv0 < LKV; kv0 += 32) {
        // Load K,V tiles 32x64 (512 float4 each, 2 per thread each)
#pragma unroll
        for (int i = 0; i < 2; i++) {
            int idx = t + i * 256;
            int r = idx >> 4, c = (idx & 15) << 2;
            float4 kv = *(const float4*)&Kp[(size_t)(kv0 + r) * HD + c];
            Ks[r][c + 0] = kv.x; Ks[r][c + 1] = kv.y; Ks[r][c + 2] = kv.z; Ks[r][c + 3] = kv.w;
            float4 vv = *(const float4*)&Vp[(size_t)(kv0 + r) * HD + c];
            *(float4*)&Vs[r][c] = vv;
        }
        __syncthreads();

        // S = Q K^T for 4(q) x 2(kv) per thread
        float s[4][2] = {};
#pragma unroll 16
        for (int k = 0; k < 64; k++) {
            float k0 = Ks[(tx << 1) + 0][k];
            float k1 = Ks[(tx << 1) + 1][k];
#pragma unroll
            for (int i = 0; i < 4; i++) {
                float q = Qs[(ty << 2) + i][k];
                s[i][0] += q * k0;
                s[i][1] += q * k1;
            }
        }

        // online softmax (row groups of 16 threads sharing ty)
#pragma unroll
        for (int i = 0; i < 4; i++) {
            s[i][0] *= 0.125f;
            s[i][1] *= 0.125f;
            float mx = fmaxf(s[i][0], s[i][1]);
#pragma unroll
            for (int m = 1; m < 16; m <<= 1)
                mx = fmaxf(mx, __shfl_xor_sync(0xffffffffu, mx, m));
            float mnew  = fmaxf(m_i[i], mx);
            float alpha = __expf(m_i[i] - mnew);
            float p0 = __expf(s[i][0] - mnew);
            float p1 = __expf(s[i][1] - mnew);
            float rs = p0 + p1;
#pragma unroll
            for (int m = 1; m < 16; m <<= 1)
                rs += __shfl_xor_sync(0xffffffffu, rs, m);
            l_i[i] = l_i[i] * alpha + rs;
            m_i[i] = mnew;
#pragma unroll
            for (int j = 0; j < 4; j++) O[i][j] *= alpha;
            Ps[(ty << 2) + i][(tx << 1) + 0] = p0;
            Ps[(ty << 2) + i][(tx << 1) + 1] = p1;
        }
        __syncthreads();

        // O += P @ V  (4(q) x 4(hd) per thread)
#pragma unroll 8
        for (int k = 0; k < 32; k++) {
            float4 v4 = *(const float4*)&Vs[k][tx << 2];
#pragma unroll
            for (int i = 0; i < 4; i++) {
                float p = Ps[(ty << 2) + i][k];
                O[i][0] += p * v4.x;
                O[i][1] += p * v4.y;
                O[i][2] += p * v4.z;
                O[i][3] += p * v4.w;
            }
        }
        __syncthreads();
    }

    const int b = bh >> 4, h = bh & 15;
#pragma unroll
    for (int i = 0; i < 4; i++) {
        float inv = 1.0f / l_i[i];
        int l = q0 + (ty << 2) + i;
        float4 o;
        o.x = O[i][0] * inv; o.y = O[i][1] * inv;
        o.z = O[i][2] * inv; o.w = O[i][3] * inv;
        *(float4*)&g_ctx[((size_t)(b * LQ + l)) * D + h * HD + (tx << 2)] = o;
    }
}

// ---------------------------------------------------------------------------
// LayerNorm over last dim (1024), one block per row.
// ---------------------------------------------------------------------------
__global__ __launch_bounds__(256) void ln_kernel(
    const float* __restrict__ gamma, const float* __restrict__ beta,
    float* __restrict__ out)
{
    __shared__ float red[8];
    const int row = blockIdx.x;
    const int t   = threadIdx.x;
    const float* x = g_X + (size_t)row * D;

    float4 xv = *(const float4*)&x[t << 2];
    float s = xv.x + xv.y + xv.z + xv.w;
#pragma unroll
    for (int m = 16; m > 0; m >>= 1) s += __shfl_xor_sync(0xffffffffu, s, m);
    if ((t & 31) == 0) red[t >> 5] = s;
    __syncthreads();
    float tot = 0.f;
#pragma unroll
    for (int i = 0; i < 8; i++) tot += red[i];
    float mu = tot * (1.0f / D);

    float d0 = xv.x - mu, d1 = xv.y - mu, d2 = xv.z - mu, d3 = xv.w - mu;
    float ss = d0 * d0 + d1 * d1 + d2 * d2 + d3 * d3;
#pragma unroll
    for (int m = 16; m > 0; m >>= 1) ss += __shfl_xor_sync(0xffffffffu, ss, m);
    __syncthreads();
    if ((t & 31) == 0) red[t >> 5] = ss;
    __syncthreads();
    float vtot = 0.f;
#pragma unroll
    for (int i = 0; i < 8; i++) vtot += red[i];
    float inv = rsqrtf(vtot * (1.0f / D) + EPS);

    float4 g  = *(const float4*)&gamma[t << 2];
    float4 be = *(const float4*)&beta[t << 2];
    float4 o;
    o.x = d0 * inv * g.x + be.x;
    o.y = d1 * inv * g.y + be.y;
    o.z = d2 * inv * g.z + be.z;
    o.w = d3 * inv * g.w + be.w;
    *(float4*)&out[(size_t)row * D + (t << 2)] = o;
}

// ---------------------------------------------------------------------------
extern "C" void kernel_launch(void* const* d_in, const int* in_sizes, int n_in,
                              void* d_out, int out_size)
{
    (void)in_sizes; (void)n_in; (void)out_size;
    const float* query     = (const float*)d_in[0];
    const float* key_value = (const float*)d_in[1];
    const float* Wq = (const float*)d_in[2];
    const float* bq = (const float*)d_in[3];
    const float* Wk = (const float*)d_in[4];
    const float* bk = (const float*)d_in[5];
    const float* Wv = (const float*)d_in[6];
    const float* bv = (const float*)d_in[7];
    const float* Wo = (const float*)d_in[8];
    const float* bo = (const float*)d_in[9];
    const float* gamma = (const float*)d_in[10];
    const float* beta  = (const float*)d_in[11];
    float* out = (float*)d_out;

    dim3 ggrid(D / 64, MTOT / 64);   // (16, 64)

    gemm_kernel<0><<<ggrid, 256>>>(query,     Wq, bq, nullptr, 0);
    gemm_kernel<0><<<ggrid, 256>>>(key_value, Wk, bk, nullptr, 1);
    gemm_kernel<0><<<ggrid, 256>>>(key_value, Wv, bv, nullptr, 2);

    attn_kernel<<<dim3(LQ / 64, B_ * NH), 256>>>();

    gemm_kernel<1><<<ggrid, 256>>>(nullptr, Wo, bo, query, 3);

    ln_kernel<<<MTOT, 256>>>(gamma, beta, out);
}

// round 7
// speedup vs baseline: 1.4121x; 1.4121x over previous
#include <cuda_runtime.h>
#include <cstdint>

#define B_   2
#define LQ   2048
#define LKV  2048
#define D    1024
#define NH   16
#define HD   64
#define MTOT (B_ * LQ)
#define LBH  (B_ * NH)
#define EPS  1e-5f
#define QSZ  4194304           // 4096*1024

// ---------------------------------------------------------------------------
// Scratch (static __device__, allocation-free).
// RULE (learned R3-R6): NEVER pass these as kernel arguments from host —
// host sees the shadow symbol, and GB300 ATS silently dereferences it.
// All scratch access happens via device-side symbol references only.
// ---------------------------------------------------------------------------
__device__ float g_WTq[1048576], g_WTk[1048576], g_WTv[1048576], g_WTo[1048576];
__device__ float g_Q[QSZ], g_K[QSZ], g_V[QSZ];   // head-major projections
__device__ float g_ctx[QSZ];
__device__ float g_X[QSZ];

// ---------------------------------------------------------------------------
// helpers
// ---------------------------------------------------------------------------
__device__ __forceinline__ void cp16f(float* s, const float* g) {
    uint32_t sa;
    asm("{ .reg .u64 t; cvta.to.shared.u64 t, %1; cvt.u32.u64 %0, t; }"
        : "=r"(sa) : "l"(s));
    asm volatile("cp.async.cg.shared.global [%0], [%1], 16;" :: "r"(sa), "l"(g) : "memory");
}
#define CP_COMMIT()  asm volatile("cp.async.commit_group;" ::: "memory")
#define CP_WAIT0()   asm volatile("cp.async.wait_group 0;" ::: "memory")

__device__ __forceinline__ uint32_t f2tf32(float f) {
    uint32_t u;
    asm("cvt.rna.tf32.f32 %0, %1;" : "=r"(u) : "f"(f));
    return u;
}

__device__ __forceinline__ void mma_tf32(float* c, uint32_t a0, uint32_t a1,
                                         uint32_t a2, uint32_t a3,
                                         uint32_t b0, uint32_t b1) {
    asm volatile(
        "mma.sync.aligned.m16n8k8.row.col.f32.tf32.tf32.f32 "
        "{%0,%1,%2,%3},{%4,%5,%6,%7},{%8,%9},{%0,%1,%2,%3};"
        : "+f"(c[0]), "+f"(c[1]), "+f"(c[2]), "+f"(c[3])
        : "r"(a0), "r"(a1), "r"(a2), "r"(a3), "r"(b0), "r"(b1));
}

// ---------------------------------------------------------------------------
// tf32 warp-MMA GEMM:  C[M,1024] = A[M,1024] @ W   (uses WT[N,K] device scratch)
// Block 128x128, BK=32, 256 thr (8 warps as 2(M) x 4(N), warp tile 64x32).
// E=0: A = harness input arg; out = g_Q/g_K/g_V by sel (+bias, head-major)
// E=1: A = g_ctx (device symbol); X = A @ Wo + bias + resid -> g_X
// sel: 0..3 selects g_WTq/g_WTk/g_WTv/g_WTo as B, and g_Q/g_K/g_V as out.
// ---------------------------------------------------------------------------
#define KK 1024
#define TSTR 36

template <int E>
__global__ __launch_bounds__(256, 1) void tgemm(
    const float* __restrict__ Ain,
    int sel, const float* __restrict__ bias, const float* __restrict__ resid)
{
    __shared__ float sA[128 * TSTR];
    __shared__ float sB[128 * TSTR];

    // device-side scratch selection (no host-passed device symbols!)
    const float* B = (sel == 0) ? g_WTq : (sel == 1) ? g_WTk
                   : (sel == 2) ? g_WTv : g_WTo;
    const float* A = (E == 1) ? g_ctx : Ain;

    const int tid  = threadIdx.x;
    const int lane = tid & 31;
    const int w    = tid >> 5;
    const int wm   = w & 1;          // 0..1 (M)
    const int wn   = w >> 1;         // 0..3 (N)
    const int m0 = blockIdx.y * 128, n0 = blockIdx.x * 128;

    float c[4][4][4];
#pragma unroll
    for (int i = 0; i < 4; i++)
#pragma unroll
        for (int j = 0; j < 4; j++)
#pragma unroll
            for (int q = 0; q < 4; q++) c[i][j][q] = 0.f;

    const int arow = wm * 64 + (lane >> 2);
    const int acol = lane & 3;
    const int brow = wn * 32 + (lane >> 2);

    for (int kb = 0; kb < KK; kb += 32) {
        // stage A,B tiles: 128 rows x 32 floats = 8 float4-chunks/row
#pragma unroll
        for (int i = 0; i < 4; i++) {
            int idx = tid + i * 256;           // 0..1023
            int r = idx >> 3, ch = idx & 7;
            int so = r * TSTR + ch * 4;
            cp16f(sA + so, A + (size_t)(m0 + r) * KK + kb + ch * 4);
            cp16f(sB + so, B + (size_t)(n0 + r) * KK + kb + ch * 4);
        }
        CP_COMMIT();
        CP_WAIT0();
        __syncthreads();

#pragma unroll
        for (int ks = 0; ks < 4; ks++) {
            const int ko = ks * 8;
            uint32_t af[4][4], bf[4][2];
#pragma unroll
            for (int mf = 0; mf < 4; mf++) {
                int base = (arow + mf * 16) * TSTR + acol + ko;
                af[mf][0] = f2tf32(sA[base]);
                af[mf][1] = f2tf32(sA[base + 8 * TSTR]);
                af[mf][2] = f2tf32(sA[base + 4]);
                af[mf][3] = f2tf32(sA[base + 8 * TSTR + 4]);
            }
#pragma unroll
            for (int nf = 0; nf < 4; nf++) {
                int bb = (brow + nf * 8) * TSTR + acol + ko;
                bf[nf][0] = f2tf32(sB[bb]);
                bf[nf][1] = f2tf32(sB[bb + 4]);
            }
#pragma unroll
            for (int mf = 0; mf < 4; mf++)
#pragma unroll
                for (int nf = 0; nf < 4; nf++)
                    mma_tf32(c[mf][nf], af[mf][0], af[mf][1], af[mf][2], af[mf][3],
                             bf[nf][0], bf[nf][1]);
        }
        __syncthreads();
    }

    // ---- epilogue ----
#pragma unroll
    for (int mf = 0; mf < 4; mf++)
#pragma unroll
        for (int nf = 0; nf < 4; nf++)
#pragma unroll
            for (int half = 0; half < 2; half++) {
                int m = m0 + wm * 64 + mf * 16 + (lane >> 2) + half * 8;
                int n = n0 + wn * 32 + nf * 8 + (lane & 3) * 2;
                float2 v = make_float2(c[mf][nf][half * 2], c[mf][nf][half * 2 + 1]);

                if constexpr (E == 0) {
                    v.x += __ldg(&bias[n]); v.y += __ldg(&bias[n + 1]);
                    float* outp = (sel == 0) ? g_Q : (sel == 1) ? g_K : g_V;
                    size_t dst = (((size_t)((m >> 11) * NH + (n >> 6))) * LQ + (m & 2047)) * HD + (n & 63);
                    *(float2*)(outp + dst) = v;
                } else {
                    size_t idx = (size_t)m * D + n;
                    float2 r4 = *(const float2*)(resid + idx);
                    v.x += __ldg(&bias[n]) + r4.x;
                    v.y += __ldg(&bias[n + 1]) + r4.y;
                    *(float2*)(g_X + idx) = v;
                }
            }
}

// ---------------------------------------------------------------------------
// fp32 transpose: x[1024][1024] (harness W) -> g_WT*[osel][1024][1024]^T
// ---------------------------------------------------------------------------
__global__ __launch_bounds__(256) void wtrans(
    const float* __restrict__ x, int osel)
{
    float* y = (osel == 0) ? g_WTq : (osel == 1) ? g_WTk
             : (osel == 2) ? g_WTv : g_WTo;

    __shared__ float t[32][33];
    const int c0 = blockIdx.x * 32, r0 = blockIdx.y * 32;
    const int tx = threadIdx.x, ty = threadIdx.y;

#pragma unroll
    for (int i = 0; i < 4; i++)
        t[ty + 8 * i][tx] = x[(size_t)(r0 + ty + 8 * i) * KK + c0 + tx];
    __syncthreads();
#pragma unroll
    for (int i = 0; i < 4; i++)
        y[(size_t)(c0 + ty + 8 * i) * KK + r0 + tx] = t[tx][ty + 8 * i];
}

// ---------------------------------------------------------------------------
// Flash attention (PROVEN R0 code): per block = one (b,h) x 64 q-rows.
// All scratch via device symbols.
// ---------------------------------------------------------------------------
__global__ __launch_bounds__(256) void attn_kernel()
{
    __shared__ float Qs[64][65];
    __shared__ float Ks[32][65];
    __shared__ float Vs[32][64];
    __shared__ float Ps[64][33];

    const int bh = blockIdx.y;
    const int q0 = blockIdx.x * 64;
    const float* Qp = g_Q + ((size_t)bh * LQ + q0) * HD;
    const float* Kp = g_K + (size_t)bh * LKV * HD;
    const float* Vp = g_V + (size_t)bh * LKV * HD;

    const int t  = threadIdx.x;
    const int tx = t & 15;
    const int ty = t >> 4;

#pragma unroll
    for (int i = 0; i < 4; i++) {
        int idx = t + i * 256;
        int r = idx >> 4, c = (idx & 15) << 2;
        float4 v = *(const float4*)&Qp[r * HD + c];
        Qs[r][c + 0] = v.x; Qs[r][c + 1] = v.y; Qs[r][c + 2] = v.z; Qs[r][c + 3] = v.w;
    }

    float m_i[4], l_i[4], O[4][4] = {};
#pragma unroll
    for (int i = 0; i < 4; i++) { m_i[i] = -1e30f; l_i[i] = 0.f; }

    for (int kv0 = 0; kv0 < LKV; kv0 += 32) {
#pragma unroll
        for (int i = 0; i < 2; i++) {
            int idx = t + i * 256;
            int r = idx >> 4, c = (idx & 15) << 2;
            float4 kv = *(const float4*)&Kp[(size_t)(kv0 + r) * HD + c];
            Ks[r][c + 0] = kv.x; Ks[r][c + 1] = kv.y; Ks[r][c + 2] = kv.z; Ks[r][c + 3] = kv.w;
            float4 vv = *(const float4*)&Vp[(size_t)(kv0 + r) * HD + c];
            *(float4*)&Vs[r][c] = vv;
        }
        __syncthreads();

        float s[4][2] = {};
#pragma unroll 16
        for (int k = 0; k < 64; k++) {
            float k0 = Ks[(tx << 1) + 0][k];
            float k1 = Ks[(tx << 1) + 1][k];
#pragma unroll
            for (int i = 0; i < 4; i++) {
                float q = Qs[(ty << 2) + i][k];
                s[i][0] += q * k0;
                s[i][1] += q * k1;
            }
        }

#pragma unroll
        for (int i = 0; i < 4; i++) {
            s[i][0] *= 0.125f;
            s[i][1] *= 0.125f;
            float mx = fmaxf(s[i][0], s[i][1]);
#pragma unroll
            for (int m = 1; m < 16; m <<= 1)
                mx = fmaxf(mx, __shfl_xor_sync(0xffffffffu, mx, m));
            float mnew  = fmaxf(m_i[i], mx);
            float alpha = __expf(m_i[i] - mnew);
            float p0 = __expf(s[i][0] - mnew);
            float p1 = __expf(s[i][1] - mnew);
            float rs = p0 + p1;
#pragma unroll
            for (int m = 1; m < 16; m <<= 1)
                rs += __shfl_xor_sync(0xffffffffu, rs, m);
            l_i[i] = l_i[i] * alpha + rs;
            m_i[i] = mnew;
#pragma unroll
            for (int j = 0; j < 4; j++) O[i][j] *= alpha;
            Ps[(ty << 2) + i][(tx << 1) + 0] = p0;
            Ps[(ty << 2) + i][(tx << 1) + 1] = p1;
        }
        __syncthreads();

#pragma unroll 8
        for (int k = 0; k < 32; k++) {
            float4 v4 = *(const float4*)&Vs[k][tx << 2];
#pragma unroll
            for (int i = 0; i < 4; i++) {
                float p = Ps[(ty << 2) + i][k];
                O[i][0] += p * v4.x;
                O[i][1] += p * v4.y;
                O[i][2] += p * v4.z;
                O[i][3] += p * v4.w;
            }
        }
        __syncthreads();
    }

    const int b = bh >> 4, h = bh & 15;
#pragma unroll
    for (int i = 0; i < 4; i++) {
        float inv = 1.0f / l_i[i];
        int l = q0 + (ty << 2) + i;
        float4 o;
        o.x = O[i][0] * inv; o.y = O[i][1] * inv;
        o.z = O[i][2] * inv; o.w = O[i][3] * inv;
        *(float4*)&g_ctx[((size_t)(b * LQ + l)) * D + h * HD + (tx << 2)] = o;
    }
}

// ---------------------------------------------------------------------------
// LayerNorm over last dim (1024); reads g_X via device symbol
// ---------------------------------------------------------------------------
__global__ __launch_bounds__(256) void ln_kernel(
    const float* __restrict__ gamma, const float* __restrict__ beta,
    float* __restrict__ out)
{
    __shared__ float red[8];
    const int row = blockIdx.x;
    const int t   = threadIdx.x;
    const float* x = g_X + (size_t)row * D;

    float4 xv = *(const float4*)&x[t << 2];
    float s = xv.x + xv.y + xv.z + xv.w;
#pragma unroll
    for (int m = 16; m > 0; m >>= 1) s += __shfl_xor_sync(0xffffffffu, s, m);
    if ((t & 31) == 0) red[t >> 5] = s;
    __syncthreads();
    float tot = 0.f;
#pragma unroll
    for (int i = 0; i < 8; i++) tot += red[i];
    float mu = tot * (1.0f / D);

    float d0 = xv.x - mu, d1 = xv.y - mu, d2 = xv.z - mu, d3 = xv.w - mu;
    float ss = d0 * d0 + d1 * d1 + d2 * d2 + d3 * d3;
#pragma unroll
    for (int m = 16; m > 0; m >>= 1) ss += __shfl_xor_sync(0xffffffffu, ss, m);
    __syncthreads();
    if ((t & 31) == 0) red[t >> 5] = ss;
    __syncthreads();
    float vtot = 0.f;
#pragma unroll
    for (int i = 0; i < 8; i++) vtot += red[i];
    float inv = rsqrtf(vtot * (1.0f / D) + EPS);

    float4 g  = *(const float4*)&gamma[t << 2];
    float4 be = *(const float4*)&beta[t << 2];
    float4 o;
    o.x = d0 * inv * g.x + be.x;
    o.y = d1 * inv * g.y + be.y;
    o.z = d2 * inv * g.z + be.z;
    o.w = d3 * inv * g.w + be.w;
    *(float4*)&out[(size_t)row * D + (t << 2)] = o;
}

// ---------------------------------------------------------------------------
extern "C" void kernel_launch(void* const* d_in, const int* in_sizes, int n_in,
                              void* d_out, int out_size)
{
    (void)in_sizes; (void)n_in; (void)out_size;
    const float* query     = (const float*)d_in[0];
    const float* key_value = (const float*)d_in[1];
    const float* Wq = (const float*)d_in[2];
    const float* bq = (const float*)d_in[3];
    const float* Wk = (const float*)d_in[4];
    const float* bk = (const float*)d_in[5];
    const float* Wv = (const float*)d_in[6];
    const float* bv = (const float*)d_in[7];
    const float* Wo = (const float*)d_in[8];
    const float* bo = (const float*)d_in[9];
    const float* gamma = (const float*)d_in[10];
    const float* beta  = (const float*)d_in[11];
    float* out = (float*)d_out;

    // 1. transpose weights into device scratch (selected device-side)
    wtrans<<<dim3(32, 32), dim3(32, 8)>>>(Wq, 0);
    wtrans<<<dim3(32, 32), dim3(32, 8)>>>(Wk, 1);
    wtrans<<<dim3(32, 32), dim3(32, 8)>>>(Wv, 2);
    wtrans<<<dim3(32, 32), dim3(32, 8)>>>(Wo, 3);

    // 2. Q/K/V projections (tf32 tensor cores, head-major fp32 out)
    dim3 pg(8, 32);
    tgemm<0><<<pg, 256>>>(query,     0, bq, nullptr);
    tgemm<0><<<pg, 256>>>(key_value, 1, bk, nullptr);
    tgemm<0><<<pg, 256>>>(key_value, 2, bv, nullptr);

    // 3. attention (proven fp32 flash kernel)
    attn_kernel<<<dim3(LQ / 64, LBH), 256>>>();

    // 4. output projection + residual (tf32), A = g_ctx device-side
    tgemm<1><<<pg, 256>>>(nullptr, 3, bo, query);

    // 5. LayerNorm
    ln_kernel<<<MTOT, 256>>>(gamma, beta, out);
}

// round 8
// speedup vs baseline: 2.5692x; 1.8194x over previous
#include <cuda_runtime.h>
#include <cstdint>

#define B_   2
#define LQ   2048
#define LKV  2048
#define D    1024
#define NH   16
#define HD   64
#define MTOT (B_ * LQ)
#define LBH  (B_ * NH)
#define EPS  1e-5f
#define QSZ  4194304           // 4096*1024

// ---------------------------------------------------------------------------
// Scratch (static __device__, allocation-free).
// RULE (learned R3-R6): NEVER pass these as kernel arguments from host —
// host sees the shadow symbol, and GB300 ATS silently dereferences it.
// ---------------------------------------------------------------------------
__device__ float g_WTq[1048576], g_WTk[1048576], g_WTv[1048576], g_WTo[1048576];
__device__ float g_Q[QSZ], g_K[QSZ], g_V[QSZ];   // head-major projections
__device__ float g_ctx[QSZ];
__device__ float g_X[QSZ];

// ---------------------------------------------------------------------------
// helpers
// ---------------------------------------------------------------------------
__device__ __forceinline__ void cp16f(float* s, const float* g) {
    uint32_t sa;
    asm("{ .reg .u64 t; cvta.to.shared.u64 t, %1; cvt.u32.u64 %0, t; }"
        : "=r"(sa) : "l"(s));
    asm volatile("cp.async.cg.shared.global [%0], [%1], 16;" :: "r"(sa), "l"(g) : "memory");
}
#define CP_COMMIT()  asm volatile("cp.async.commit_group;" ::: "memory")
#define CP_WAIT0()   asm volatile("cp.async.wait_group 0;" ::: "memory")

__device__ __forceinline__ uint32_t f2tf32(float f) {
    uint32_t u;
    asm("cvt.rna.tf32.f32 %0, %1;" : "=r"(u) : "f"(f));
    return u;
}

__device__ __forceinline__ void mma_tf32(float* c, uint32_t a0, uint32_t a1,
                                         uint32_t a2, uint32_t a3,
                                         uint32_t b0, uint32_t b1) {
    asm volatile(
        "mma.sync.aligned.m16n8k8.row.col.f32.tf32.tf32.f32 "
        "{%0,%1,%2,%3},{%4,%5,%6,%7},{%8,%9},{%0,%1,%2,%3};"
        : "+f"(c[0]), "+f"(c[1]), "+f"(c[2]), "+f"(c[3])
        : "r"(a0), "r"(a1), "r"(a2), "r"(a3), "r"(b0), "r"(b1));
}

// ---------------------------------------------------------------------------
// tf32 warp-MMA GEMM (unchanged from R7 — passing): C = A @ W via WT scratch
// ---------------------------------------------------------------------------
#define KK 1024
#define TSTR 36

template <int E>
__global__ __launch_bounds__(256, 1) void tgemm(
    const float* __restrict__ Ain,
    int sel, const float* __restrict__ bias, const float* __restrict__ resid)
{
    __shared__ float sA[128 * TSTR];
    __shared__ float sB[128 * TSTR];

    const float* B = (sel == 0) ? g_WTq : (sel == 1) ? g_WTk
                   : (sel == 2) ? g_WTv : g_WTo;
    const float* A = (E == 1) ? g_ctx : Ain;

    const int tid  = threadIdx.x;
    const int lane = tid & 31;
    const int w    = tid >> 5;
    const int wm   = w & 1;
    const int wn   = w >> 1;
    const int m0 = blockIdx.y * 128, n0 = blockIdx.x * 128;

    float c[4][4][4];
#pragma unroll
    for (int i = 0; i < 4; i++)
#pragma unroll
        for (int j = 0; j < 4; j++)
#pragma unroll
            for (int q = 0; q < 4; q++) c[i][j][q] = 0.f;

    const int arow = wm * 64 + (lane >> 2);
    const int acol = lane & 3;
    const int brow = wn * 32 + (lane >> 2);

    for (int kb = 0; kb < KK; kb += 32) {
#pragma unroll
        for (int i = 0; i < 4; i++) {
            int idx = tid + i * 256;
            int r = idx >> 3, ch = idx & 7;
            int so = r * TSTR + ch * 4;
            cp16f(sA + so, A + (size_t)(m0 + r) * KK + kb + ch * 4);
            cp16f(sB + so, B + (size_t)(n0 + r) * KK + kb + ch * 4);
        }
        CP_COMMIT();
        CP_WAIT0();
        __syncthreads();

#pragma unroll
        for (int ks = 0; ks < 4; ks++) {
            const int ko = ks * 8;
            uint32_t af[4][4], bf[4][2];
#pragma unroll
            for (int mf = 0; mf < 4; mf++) {
                int base = (arow + mf * 16) * TSTR + acol + ko;
                af[mf][0] = f2tf32(sA[base]);
                af[mf][1] = f2tf32(sA[base + 8 * TSTR]);
                af[mf][2] = f2tf32(sA[base + 4]);
                af[mf][3] = f2tf32(sA[base + 8 * TSTR + 4]);
            }
#pragma unroll
            for (int nf = 0; nf < 4; nf++) {
                int bb = (brow + nf * 8) * TSTR + acol + ko;
                bf[nf][0] = f2tf32(sB[bb]);
                bf[nf][1] = f2tf32(sB[bb + 4]);
            }
#pragma unroll
            for (int mf = 0; mf < 4; mf++)
#pragma unroll
                for (int nf = 0; nf < 4; nf++)
                    mma_tf32(c[mf][nf], af[mf][0], af[mf][1], af[mf][2], af[mf][3],
                             bf[nf][0], bf[nf][1]);
        }
        __syncthreads();
    }

#pragma unroll
    for (int mf = 0; mf < 4; mf++)
#pragma unroll
        for (int nf = 0; nf < 4; nf++)
#pragma unroll
            for (int half = 0; half < 2; half++) {
                int m = m0 + wm * 64 + mf * 16 + (lane >> 2) + half * 8;
                int n = n0 + wn * 32 + nf * 8 + (lane & 3) * 2;
                float2 v = make_float2(c[mf][nf][half * 2], c[mf][nf][half * 2 + 1]);

                if constexpr (E == 0) {
                    v.x += __ldg(&bias[n]); v.y += __ldg(&bias[n + 1]);
                    float* outp = (sel == 0) ? g_Q : (sel == 1) ? g_K : g_V;
                    size_t dst = (((size_t)((m >> 11) * NH + (n >> 6))) * LQ + (m & 2047)) * HD + (n & 63);
                    *(float2*)(outp + dst) = v;
                } else {
                    size_t idx = (size_t)m * D + n;
                    float2 r4 = *(const float2*)(resid + idx);
                    v.x += __ldg(&bias[n]) + r4.x;
                    v.y += __ldg(&bias[n + 1]) + r4.y;
                    *(float2*)(g_X + idx) = v;
                }
            }
}

// ---------------------------------------------------------------------------
// fp32 transpose: harness W -> g_WT* (device-side selection)
// ---------------------------------------------------------------------------
__global__ __launch_bounds__(256) void wtrans(
    const float* __restrict__ x, int osel)
{
    float* y = (osel == 0) ? g_WTq : (osel == 1) ? g_WTk
             : (osel == 2) ? g_WTv : g_WTo;

    __shared__ float t[32][33];
    const int c0 = blockIdx.x * 32, r0 = blockIdx.y * 32;
    const int tx = threadIdx.x, ty = threadIdx.y;

#pragma unroll
    for (int i = 0; i < 4; i++)
        t[ty + 8 * i][tx] = x[(size_t)(r0 + ty + 8 * i) * KK + c0 + tx];
    __syncthreads();
#pragma unroll
    for (int i = 0; i < 4; i++)
        y[(size_t)(c0 + ty + 8 * i) * KK + r0 + tx] = t[tx][ty + 8 * i];
}

// ---------------------------------------------------------------------------
// Tensor-core flash attention (tf32 mma.sync).
// Block: 128 q-rows of one (b,h). 8 warps x 16 q-rows. KV tile = 64.
// Q frags in regs; K smem stride 68 (==4 mod 32), V smem stride 72 (==8 mod 32):
// both fragment read patterns provably conflict-free.
// P re-laid into A-fragments via warp shuffles (no smem round trip).
// ---------------------------------------------------------------------------
#define KSTR 68
#define VSTR 72

__global__ __launch_bounds__(256, 1) void attn_tc()
{
    __shared__ float sK[64 * KSTR];
    __shared__ float sV[64 * VSTR];

    const int bh = blockIdx.y;
    const int q0 = blockIdx.x * 128;
    const float* Qp = g_Q + (size_t)bh * LQ * HD;
    const float* Kp = g_K + (size_t)bh * LKV * HD;
    const float* Vp = g_V + (size_t)bh * LKV * HD;

    const int tid  = threadIdx.x;
    const int lane = tid & 31;
    const int w    = tid >> 5;
    const int qr   = lane >> 2;       // 0..7
    const int qc   = lane & 3;        // 0..3 (quad pos)

    // ---- load Q fragments (16 rows per warp, k = 64 -> 8 k-steps) ----
    uint32_t qf[8][4];
    {
        const int r0 = q0 + w * 16 + qr;
#pragma unroll
        for (int ks = 0; ks < 8; ks++) {
            int k = ks * 8 + qc;
            qf[ks][0] = f2tf32(__ldg(Qp + (size_t)r0 * HD + k));
            qf[ks][1] = f2tf32(__ldg(Qp + (size_t)(r0 + 8) * HD + k));
            qf[ks][2] = f2tf32(__ldg(Qp + (size_t)r0 * HD + k + 4));
            qf[ks][3] = f2tf32(__ldg(Qp + (size_t)(r0 + 8) * HD + k + 4));
        }
    }

    float o[8][4];
#pragma unroll
    for (int i = 0; i < 8; i++)
#pragma unroll
        for (int j = 0; j < 4; j++) o[i][j] = 0.f;
    float m_i[2] = {-1e30f, -1e30f};
    float l_i[2] = {0.f, 0.f};

    const int srcA = (lane & ~3) | (qc >> 1);       // shuffle sources
    const int srcB = srcA + 2;

    for (int kv0 = 0; kv0 < LKV; kv0 += 64) {
        // stage K (stride 68) and V (stride 72): 64 rows x 16 float4 each
#pragma unroll
        for (int i = 0; i < 4; i++) {
            int idx = tid + i * 256;
            int r = idx >> 4, ch = idx & 15;
            cp16f(sK + r * KSTR + ch * 4, Kp + (size_t)(kv0 + r) * HD + ch * 4);
            cp16f(sV + r * VSTR + ch * 4, Vp + (size_t)(kv0 + r) * HD + ch * 4);
        }
        CP_COMMIT();
        CP_WAIT0();
        __syncthreads();

        // ---- S = Q K^T ----
        float s[8][4];
#pragma unroll
        for (int i = 0; i < 8; i++)
#pragma unroll
            for (int j = 0; j < 4; j++) s[i][j] = 0.f;

#pragma unroll
        for (int ks = 0; ks < 8; ks++) {
            const int ko = ks * 8;
#pragma unroll
            for (int nf = 0; nf < 8; nf++) {
                int bb = (nf * 8 + qr) * KSTR + ko + qc;
                uint32_t b0 = f2tf32(sK[bb]);
                uint32_t b1 = f2tf32(sK[bb + 4]);
                mma_tf32(s[nf], qf[ks][0], qf[ks][1], qf[ks][2], qf[ks][3], b0, b1);
            }
        }

        // ---- online softmax (rows qr and qr+8, quad-shared) ----
        float mx0 = -1e30f, mx1 = -1e30f;
#pragma unroll
        for (int nf = 0; nf < 8; nf++) {
            s[nf][0] *= 0.125f; s[nf][1] *= 0.125f;
            s[nf][2] *= 0.125f; s[nf][3] *= 0.125f;
            mx0 = fmaxf(mx0, fmaxf(s[nf][0], s[nf][1]));
            mx1 = fmaxf(mx1, fmaxf(s[nf][2], s[nf][3]));
        }
        mx0 = fmaxf(mx0, __shfl_xor_sync(0xffffffffu, mx0, 1));
        mx0 = fmaxf(mx0, __shfl_xor_sync(0xffffffffu, mx0, 2));
        mx1 = fmaxf(mx1, __shfl_xor_sync(0xffffffffu, mx1, 1));
        mx1 = fmaxf(mx1, __shfl_xor_sync(0xffffffffu, mx1, 2));

        float mn0 = fmaxf(m_i[0], mx0), mn1 = fmaxf(m_i[1], mx1);
        float al0 = __expf(m_i[0] - mn0), al1 = __expf(m_i[1] - mn1);
        m_i[0] = mn0; m_i[1] = mn1;

        float rs0 = 0.f, rs1 = 0.f;
#pragma unroll
        for (int nf = 0; nf < 8; nf++) {
            s[nf][0] = __expf(s[nf][0] - mn0);
            s[nf][1] = __expf(s[nf][1] - mn0);
            s[nf][2] = __expf(s[nf][2] - mn1);
            s[nf][3] = __expf(s[nf][3] - mn1);
            rs0 += s[nf][0] + s[nf][1];
            rs1 += s[nf][2] + s[nf][3];
        }
        rs0 += __shfl_xor_sync(0xffffffffu, rs0, 1);
        rs0 += __shfl_xor_sync(0xffffffffu, rs0, 2);
        rs1 += __shfl_xor_sync(0xffffffffu, rs1, 1);
        rs1 += __shfl_xor_sync(0xffffffffu, rs1, 2);
        l_i[0] = l_i[0] * al0 + rs0;
        l_i[1] = l_i[1] * al1 + rs1;

#pragma unroll
        for (int nf = 0; nf < 8; nf++) {
            o[nf][0] *= al0; o[nf][1] *= al0;
            o[nf][2] *= al1; o[nf][3] *= al1;
        }

        // ---- O += P V  (P re-laid via shuffles per kv k-group) ----
#pragma unroll
        for (int kg = 0; kg < 8; kg++) {
            uint32_t p0 = f2tf32(s[kg][0]), p1 = f2tf32(s[kg][1]);
            uint32_t p2 = f2tf32(s[kg][2]), p3 = f2tf32(s[kg][3]);
            uint32_t v0 = __shfl_sync(0xffffffffu, p0, srcA);
            uint32_t v1 = __shfl_sync(0xffffffffu, p1, srcA);
            uint32_t v2 = __shfl_sync(0xffffffffu, p2, srcA);
            uint32_t v3 = __shfl_sync(0xffffffffu, p3, srcA);
            uint32_t w0 = __shfl_sync(0xffffffffu, p0, srcB);
            uint32_t w1 = __shfl_sync(0xffffffffu, p1, srcB);
            uint32_t w2 = __shfl_sync(0xffffffffu, p2, srcB);
            uint32_t w3 = __shfl_sync(0xffffffffu, p3, srcB);
            uint32_t a0 = (qc & 1) ? v1 : v0;
            uint32_t a1 = (qc & 1) ? v3 : v2;
            uint32_t a2 = (qc & 1) ? w1 : w0;
            uint32_t a3 = (qc & 1) ? w3 : w2;

            const int ko = kg * 8;
#pragma unroll
            for (int nf = 0; nf < 8; nf++) {
                int bb = (ko + qc) * VSTR + nf * 8 + qr;
                uint32_t b0 = f2tf32(sV[bb]);
                uint32_t b1 = f2tf32(sV[bb + 4 * VSTR]);
                mma_tf32(o[nf], a0, a1, a2, a3, b0, b1);
            }
        }
        __syncthreads();
    }

    // ---- epilogue: O / l, scatter to g_ctx interleaved layout ----
    const int b = bh >> 4, h = bh & 15;
    const float inv0 = 1.0f / l_i[0], inv1 = 1.0f / l_i[1];
    const int r0 = q0 + w * 16 + qr;
#pragma unroll
    for (int nf = 0; nf < 8; nf++) {
        int col = h * HD + nf * 8 + qc * 2;
        float2 u0 = make_float2(o[nf][0] * inv0, o[nf][1] * inv0);
        float2 u1 = make_float2(o[nf][2] * inv1, o[nf][3] * inv1);
        *(float2*)(g_ctx + (size_t)(b * LQ + r0) * D + col)       = u0;
        *(float2*)(g_ctx + (size_t)(b * LQ + r0 + 8) * D + col)   = u1;
    }
}

// ---------------------------------------------------------------------------
// LayerNorm over last dim (1024)
// ---------------------------------------------------------------------------
__global__ __launch_bounds__(256) void ln_kernel(
    const float* __restrict__ gamma, const float* __restrict__ beta,
    float* __restrict__ out)
{
    __shared__ float red[8];
    const int row = blockIdx.x;
    const int t   = threadIdx.x;
    const float* x = g_X + (size_t)row * D;

    float4 xv = *(const float4*)&x[t << 2];
    float s = xv.x + xv.y + xv.z + xv.w;
#pragma unroll
    for (int m = 16; m > 0; m >>= 1) s += __shfl_xor_sync(0xffffffffu, s, m);
    if ((t & 31) == 0) red[t >> 5] = s;
    __syncthreads();
    float tot = 0.f;
#pragma unroll
    for (int i = 0; i < 8; i++) tot += red[i];
    float mu = tot * (1.0f / D);

    float d0 = xv.x - mu, d1 = xv.y - mu, d2 = xv.z - mu, d3 = xv.w - mu;
    float ss = d0 * d0 + d1 * d1 + d2 * d2 + d3 * d3;
#pragma unroll
    for (int m = 16; m > 0; m >>= 1) ss += __shfl_xor_sync(0xffffffffu, ss, m);
    __syncthreads();
    if ((t & 31) == 0) red[t >> 5] = ss;
    __syncthreads();
    float vtot = 0.f;
#pragma unroll
    for (int i = 0; i < 8; i++) vtot += red[i];
    float inv = rsqrtf(vtot * (1.0f / D) + EPS);

    float4 g  = *(const float4*)&gamma[t << 2];
    float4 be = *(const float4*)&beta[t << 2];
    float4 o;
    o.x = d0 * inv * g.x + be.x;
    o.y = d1 * inv * g.y + be.y;
    o.z = d2 * inv * g.z + be.z;
    o.w = d3 * inv * g.w + be.w;
    *(float4*)&out[(size_t)row * D + (t << 2)] = o;
}

// ---------------------------------------------------------------------------
extern "C" void kernel_launch(void* const* d_in, const int* in_sizes, int n_in,
                              void* d_out, int out_size)
{
    (void)in_sizes; (void)n_in; (void)out_size;
    const float* query     = (const float*)d_in[0];
    const float* key_value = (const float*)d_in[1];
    const float* Wq = (const float*)d_in[2];
    const float* bq = (const float*)d_in[3];
    const float* Wk = (const float*)d_in[4];
    const float* bk = (const float*)d_in[5];
    const float* Wv = (const float*)d_in[6];
    const float* bv = (const float*)d_in[7];
    const float* Wo = (const float*)d_in[8];
    const float* bo = (const float*)d_in[9];
    const float* gamma = (const float*)d_in[10];
    const float* beta  = (const float*)d_in[11];
    float* out = (float*)d_out;

    // 1. transpose weights into device scratch
    wtrans<<<dim3(32, 32), dim3(32, 8)>>>(Wq, 0);
    wtrans<<<dim3(32, 32), dim3(32, 8)>>>(Wk, 1);
    wtrans<<<dim3(32, 32), dim3(32, 8)>>>(Wv, 2);
    wtrans<<<dim3(32, 32), dim3(32, 8)>>>(Wo, 3);

    // 2. Q/K/V projections (tf32 tensor cores, head-major fp32 out)
    dim3 pg(8, 32);
    tgemm<0><<<pg, 256>>>(query,     0, bq, nullptr);
    tgemm<0><<<pg, 256>>>(key_value, 1, bk, nullptr);
    tgemm<0><<<pg, 256>>>(key_value, 2, bv, nullptr);

    // 3. attention (tf32 tensor-core flash)
    attn_tc<<<dim3(LQ / 128, LBH), 256>>>();

    // 4. output projection + residual (tf32), A = g_ctx device-side
    tgemm<1><<<pg, 256>>>(nullptr, 3, bo, query);

    // 5. LayerNorm
    ln_kernel<<<MTOT, 256>>>(gamma, beta, out);
}